// round 7
// baseline (speedup 1.0000x reference)
#include <cuda_runtime.h>
#include <cuda_bf16.h>
#include <cstdint>

#define DI __device__ __forceinline__

// ---------------- problem dims ----------------
#define BB    8
#define LL    4096
#define CIN   1024
#define COUT  1024
#define WDIM  512
#define MTOT  (BB*LL)          // 32768
#define NK    16               // K tiles of 64
#define KT    64               // bf16 per K tile (128 bytes)

// ---------------- device scratch (no allocs allowed) ----------------
__device__ __align__(16) float          g_styles[BB*CIN];                     // 32 KB
__device__ __align__(16) __nv_bfloat16  g_wmod[(size_t)BB*COUT*CIN];          // 16 MB
__device__ __align__(16) __nv_bfloat16  g_xbf[(size_t)MTOT*CIN];              // 64 MB

// ---------------- PTX helpers (baseline PTX only: compute_103 target!) ----------------
DI uint32_t smem_u32(const void* p) {
    uint32_t a;
    asm("{ .reg .u64 t; cvta.to.shared.u64 t, %1; cvt.u32.u64 %0, t; }" : "=r"(a) : "l"(p));
    return a;
}
DI void cp16(uint32_t dst, const void* src) {
    asm volatile("cp.async.cg.shared.global [%0], [%1], 16;" :: "r"(dst), "l"(src));
}
DI void cp_commit() { asm volatile("cp.async.commit_group;" ::: "memory"); }
template<int N> DI void cp_wait() { asm volatile("cp.async.wait_group %0;" :: "n"(N) : "memory"); }

DI void ldm_x4(uint32_t* r, uint32_t addr) {
    asm volatile("ldmatrix.sync.aligned.m8n8.x4.shared.b16 {%0,%1,%2,%3}, [%4];"
        : "=r"(r[0]), "=r"(r[1]), "=r"(r[2]), "=r"(r[3]) : "r"(addr));
}
DI void mma16816(float* c, const uint32_t* a, uint32_t b0, uint32_t b1) {
    asm volatile("mma.sync.aligned.m16n8k16.row.col.f32.bf16.bf16.f32 "
        "{%0,%1,%2,%3}, {%4,%5,%6,%7}, {%8,%9}, {%0,%1,%2,%3};"
        : "+f"(c[0]), "+f"(c[1]), "+f"(c[2]), "+f"(c[3])
        : "r"(a[0]), "r"(a[1]), "r"(a[2]), "r"(a[3]), "r"(b0), "r"(b1));
}

// =====================================================================
// k0: styles[b,i] = (w[b,:] . aff_w[i,:]) / sqrt(512) + aff_b[i]
// one warp per output; 8192 warps
// =====================================================================
__global__ void k_styles(const float* __restrict__ w, const float* __restrict__ aw,
                         const float* __restrict__ ab) {
    int gw   = (blockIdx.x * blockDim.x + threadIdx.x) >> 5;
    int lane = threadIdx.x & 31;
    if (gw >= BB*CIN) return;
    int b = gw >> 10, i = gw & 1023;
    const float* wr = w  + b * WDIM;
    const float* ar = aw + (size_t)i * WDIM;
    float s = 0.f;
    #pragma unroll
    for (int t = 0; t < WDIM/32; t++) {
        int j = lane + 32*t;
        s += wr[j] * ar[j];
    }
    #pragma unroll
    for (int o = 16; o > 0; o >>= 1) s += __shfl_xor_sync(0xFFFFFFFFu, s, o);
    if (lane == 0)
        g_styles[gw] = s * 0.04419417382415922f + ab[i];   // 1/sqrt(512)
}

// =====================================================================
// k1: per (b,o): prod_i = weight[o,i]*styles[b,i];
//     dcoef = rsqrt(sum prod^2 + 1e-8); wmod[b,o,i] = bf16(prod_i * dcoef)
// one warp per (b,o); 8192 warps
// =====================================================================
__global__ void k_wmod(const float* __restrict__ weight) {
    int gw   = (blockIdx.x * blockDim.x + threadIdx.x) >> 5;
    int lane = threadIdx.x & 31;
    if (gw >= BB*COUT) return;
    int b = gw >> 10, o = gw & 1023;
    const float2* wr = (const float2*)(weight + (size_t)o * CIN);
    const float2* sr = (const float2*)(g_styles + b * CIN);
    float p0[16], p1[16];
    float ss = 0.f;
    #pragma unroll
    for (int t = 0; t < 16; t++) {
        int idx = lane + 32*t;
        float2 wv = wr[idx];
        float2 sv = sr[idx];
        p0[t] = wv.x * sv.x;
        p1[t] = wv.y * sv.y;
        ss += p0[t]*p0[t] + p1[t]*p1[t];
    }
    #pragma unroll
    for (int off = 16; off > 0; off >>= 1) ss += __shfl_xor_sync(0xFFFFFFFFu, ss, off);
    float d = rsqrtf(ss + 1e-8f);
    __nv_bfloat162* dst = (__nv_bfloat162*)(g_wmod + ((size_t)b * COUT + o) * CIN);
    #pragma unroll
    for (int t = 0; t < 16; t++) {
        int idx = lane + 32*t;
        float2 v; v.x = p0[t]*d; v.y = p1[t]*d;
        dst[idx] = __float22bfloat162_rn(v);
    }
}

// =====================================================================
// k2: x (fp32) -> g_xbf (bf16)
// =====================================================================
__global__ void k_xconv(const float* __restrict__ x) {
    size_t n4 = (size_t)MTOT * CIN / 4;
    size_t stride = (size_t)gridDim.x * blockDim.x;
    const float4* xv = (const float4*)x;
    uint2* dst = (uint2*)g_xbf;
    for (size_t i = (size_t)blockIdx.x * blockDim.x + threadIdx.x; i < n4; i += stride) {
        float4 v = xv[i];
        __nv_bfloat162 a = __float22bfloat162_rn(make_float2(v.x, v.y));
        __nv_bfloat162 c = __float22bfloat162_rn(make_float2(v.z, v.w));
        uint2 u;
        u.x = *reinterpret_cast<uint32_t*>(&a);
        u.y = *reinterpret_cast<uint32_t*>(&c);
        dst[i] = u;
    }
}

// =====================================================================
// k3: GEMM  out[m, n] = epilogue( xbf[m,:] @ wmod[b]^T )
// CTA 128x128, K-tile 64; mma.sync m16n8k16 bf16, 8 warps (2x4), 64x32/warp
// 4-stage cp.async ring (32 KB/stage), SW128 swizzle, ldmatrix.x4
// =====================================================================
#define STAGES      4
#define STAGE_BYTES 32768     // A 16KB + B 16KB

DI void load_stage(const __nv_bfloat16* __restrict__ gA, const __nv_bfloat16* __restrict__ gB,
                   uint32_t st, int kt, int tid) {
    const __nv_bfloat16* sA = gA + kt * KT;
    #pragma unroll
    for (int i = 0; i < 4; i++) {
        int t = tid + i * 256;
        int row = t >> 3, c = t & 7;
        uint32_t off = (uint32_t)row * 128u + (uint32_t)c * 16u;
        cp16(st + (off ^ ((off >> 3) & 0x70u)), sA + (size_t)row * CIN + c * 8);
    }
    const __nv_bfloat16* sB = gB + kt * KT;
    #pragma unroll
    for (int i = 0; i < 4; i++) {
        int t = tid + i * 256;
        int row = t >> 3, c = t & 7;
        uint32_t off = (uint32_t)row * 128u + (uint32_t)c * 16u;
        cp16(st + 16384u + (off ^ ((off >> 3) & 0x70u)), sB + (size_t)row * CIN + c * 8);
    }
}

__global__ void __launch_bounds__(256, 1)
k_gemm(const float* __restrict__ x, const float* __restrict__ bias,
       const float* __restrict__ ls, float* __restrict__ out) {
    extern __shared__ __align__(1024) char smem[];
    uint32_t sb = smem_u32(smem);
    const int tid  = threadIdx.x;
    const int wid  = tid >> 5;
    const int lane = tid & 31;
    const int m0 = blockIdx.x * 128;
    const int n0 = blockIdx.y * 128;
    const int b  = blockIdx.x >> 5;           // 4096 rows per batch
    const __nv_bfloat16* gA = g_xbf  + (size_t)m0 * CIN;
    const __nv_bfloat16* gB = g_wmod + ((size_t)b * COUT + n0) * CIN;

    const int warp_m = wid & 1;               // 0..1 -> 64-row block
    const int warp_n = wid >> 1;              // 0..3 -> 32-col block

    // ldmatrix per-lane addressing (row low bits constant across mi/njp steps of 16)
    const int aRow = warp_m * 64 + (lane & 15);
    const int bRow = warp_n * 32 + (lane & 15);
    const uint32_t halfOff = (uint32_t)(lane >> 4) * 16u;
    const uint32_t rxA = (uint32_t)(aRow & 7) << 4;
    const uint32_t rxB = (uint32_t)(bRow & 7) << 4;
    const uint32_t aBase = (uint32_t)aRow * 128u;
    const uint32_t bBase = 16384u + (uint32_t)bRow * 128u;

    float acc[4][4][4];
    #pragma unroll
    for (int i = 0; i < 4; i++)
        #pragma unroll
        for (int j = 0; j < 4; j++)
            #pragma unroll
            for (int e = 0; e < 4; e++) acc[i][j][e] = 0.f;

    // prologue: 3 stages in flight
    load_stage(gA, gB, sb + 0 * STAGE_BYTES, 0, tid); cp_commit();
    load_stage(gA, gB, sb + 1 * STAGE_BYTES, 1, tid); cp_commit();
    load_stage(gA, gB, sb + 2 * STAGE_BYTES, 2, tid); cp_commit();

    for (int kt = 0; kt < NK; kt++) {
        cp_wait<2>();
        __syncthreads();
        int jp = kt + 3;
        if (jp < NK)
            load_stage(gA, gB, sb + (jp & 3) * STAGE_BYTES, jp, tid);
        cp_commit();

        uint32_t st = sb + (kt & 3) * STAGE_BYTES;
        #pragma unroll
        for (int ks = 0; ks < 4; ks++) {
            uint32_t kA = ((uint32_t)(ks * 32) + halfOff) ^ rxA;
            uint32_t kB = ((uint32_t)(ks * 32) + halfOff) ^ rxB;
            uint32_t aF[4][4];
            #pragma unroll
            for (int mi = 0; mi < 4; mi++)
                ldm_x4(aF[mi], st + aBase + (uint32_t)mi * 2048u + kA);
            uint32_t bF[2][4];
            #pragma unroll
            for (int njp = 0; njp < 2; njp++)
                ldm_x4(bF[njp], st + bBase + (uint32_t)njp * 2048u + kB);
            #pragma unroll
            for (int mi = 0; mi < 4; mi++) {
                #pragma unroll
                for (int nj = 0; nj < 4; nj++) {
                    int njp = nj >> 1, sel = nj & 1;
                    mma16816(acc[mi][nj], aF[mi], bF[njp][sel], bF[njp][sel | 2]);
                }
            }
        }
    }

    // ---------------- fused epilogue (registers -> global) ----------------
    const float GAIN = 1.41421356237f;
    const int tm0 = m0 + warp_m * 64 + (lane >> 2);
    const int tc0 = n0 + warp_n * 32 + (lane & 3) * 2;
    float2 bi2[4], ls2[4];
    #pragma unroll
    for (int nj = 0; nj < 4; nj++) {
        int col = tc0 + nj * 8;
        bi2[nj] = make_float2(__ldg(bias + col), __ldg(bias + col + 1));
        ls2[nj] = make_float2(__ldg(ls + col),   __ldg(ls + col + 1));
    }
    #pragma unroll
    for (int mi = 0; mi < 4; mi++) {
        #pragma unroll
        for (int h = 0; h < 2; h++) {
            int m = tm0 + mi * 16 + h * 8;
            const float* xr = x   + (size_t)m * COUT;
            float*       orr = out + (size_t)m * COUT;
            #pragma unroll
            for (int nj = 0; nj < 4; nj++) {
                int col = tc0 + nj * 8;
                float c0 = acc[mi][nj][h * 2 + 0];
                float c1 = acc[mi][nj][h * 2 + 1];
                float2 xv = *(const float2*)(xr + col);
                float t0 = c0 + bi2[nj].x;
                float t1 = c1 + bi2[nj].y;
                t0 = ((t0 > 0.f) ? t0 : 0.2f * t0) * GAIN;
                t1 = ((t1 > 0.f) ? t1 : 0.2f * t1) * GAIN;
                t0 = fminf(fmaxf(t0, -256.f), 256.f);
                t1 = fminf(fmaxf(t1, -256.f), 256.f);
                float2 o2;
                o2.x = t0 * ls2[nj].x + xv.x;
                o2.y = t1 * ls2[nj].y + xv.y;
                *(float2*)(orr + col) = o2;
            }
        }
    }
}

// =====================================================================
// launch
// =====================================================================
extern "C" void kernel_launch(void* const* d_in, const int* in_sizes, int n_in,
                              void* d_out, int out_size) {
    const float* x      = (const float*)d_in[0];
    const float* w      = (const float*)d_in[1];
    const float* weight = (const float*)d_in[2];
    const float* bias   = (const float*)d_in[3];
    const float* aff_w  = (const float*)d_in[4];
    const float* aff_b  = (const float*)d_in[5];
    const float* lscale = (const float*)d_in[6];
    float* out = (float*)d_out;

    static bool attr_set = false;
    cudaFuncSetAttribute(k_gemm, cudaFuncAttributeMaxDynamicSharedMemorySize,
                         STAGES * STAGE_BYTES);
    (void)attr_set;

    k_styles<<<1024, 256>>>(w, aff_w, aff_b);
    k_wmod  <<<1024, 256>>>(weight);
    k_xconv <<<4096, 256>>>(x);

    dim3 grid(MTOT / 128, COUT / 128);   // 256 x 8
    k_gemm<<<grid, 256, STAGES * STAGE_BYTES>>>(x, bias, lscale, out);
}

// round 8
// speedup vs baseline: 1.0776x; 1.0776x over previous
#include <cuda_runtime.h>
#include <cuda_bf16.h>
#include <cstdint>

#define DI __device__ __forceinline__

// ---------------- problem dims ----------------
#define BB    8
#define LL    4096
#define CIN   1024
#define COUT  1024
#define WDIM  512
#define MTOT  (BB*LL)          // 32768
#define NK    16               // K tiles of 64
#define KT    64               // bf16 per K tile (128 bytes)

// ---------------- device scratch (no allocs allowed) ----------------
__device__ __align__(16) float          g_styles[BB*CIN];                     // 32 KB
__device__ __align__(16) __nv_bfloat16  g_wmod[(size_t)BB*COUT*CIN];          // 16 MB
__device__ __align__(16) __nv_bfloat16  g_xbf[(size_t)MTOT*CIN];              // 64 MB

// ---------------- PTX helpers (baseline PTX only: compute_103 target!) ----------------
DI uint32_t smem_u32(const void* p) {
    uint32_t a;
    asm("{ .reg .u64 t; cvta.to.shared.u64 t, %1; cvt.u32.u64 %0, t; }" : "=r"(a) : "l"(p));
    return a;
}
DI void cp16(uint32_t dst, const void* src) {
    asm volatile("cp.async.cg.shared.global [%0], [%1], 16;" :: "r"(dst), "l"(src));
}
DI void cp_commit() { asm volatile("cp.async.commit_group;" ::: "memory"); }
template<int N> DI void cp_wait() { asm volatile("cp.async.wait_group %0;" :: "n"(N) : "memory"); }

DI void ldm_x4(uint32_t* r, uint32_t addr) {
    asm volatile("ldmatrix.sync.aligned.m8n8.x4.shared.b16 {%0,%1,%2,%3}, [%4];"
        : "=r"(r[0]), "=r"(r[1]), "=r"(r[2]), "=r"(r[3]) : "r"(addr));
}
DI void mma16816(float* c, const uint32_t* a, uint32_t b0, uint32_t b1) {
    asm volatile("mma.sync.aligned.m16n8k16.row.col.f32.bf16.bf16.f32 "
        "{%0,%1,%2,%3}, {%4,%5,%6,%7}, {%8,%9}, {%0,%1,%2,%3};"
        : "+f"(c[0]), "+f"(c[1]), "+f"(c[2]), "+f"(c[3])
        : "r"(a[0]), "r"(a[1]), "r"(a[2]), "r"(a[3]), "r"(b0), "r"(b1));
}

// =====================================================================
// k0: styles[b,i] = (w[b,:] . aff_w[i,:]) / sqrt(512) + aff_b[i]
// =====================================================================
__global__ void k_styles(const float* __restrict__ w, const float* __restrict__ aw,
                         const float* __restrict__ ab) {
    int gw   = (blockIdx.x * blockDim.x + threadIdx.x) >> 5;
    int lane = threadIdx.x & 31;
    if (gw >= BB*CIN) return;
    int b = gw >> 10, i = gw & 1023;
    const float* wr = w  + b * WDIM;
    const float* ar = aw + (size_t)i * WDIM;
    float s = 0.f;
    #pragma unroll
    for (int t = 0; t < WDIM/32; t++) {
        int j = lane + 32*t;
        s += wr[j] * ar[j];
    }
    #pragma unroll
    for (int o = 16; o > 0; o >>= 1) s += __shfl_xor_sync(0xFFFFFFFFu, s, o);
    if (lane == 0)
        g_styles[gw] = s * 0.04419417382415922f + ab[i];   // 1/sqrt(512)
}

// =====================================================================
// k1: per (b,o): prod_i = weight[o,i]*styles[b,i];
//     dcoef = rsqrt(sum prod^2 + 1e-8); wmod[b,o,i] = bf16(prod_i * dcoef)
// =====================================================================
__global__ void k_wmod(const float* __restrict__ weight) {
    int gw   = (blockIdx.x * blockDim.x + threadIdx.x) >> 5;
    int lane = threadIdx.x & 31;
    if (gw >= BB*COUT) return;
    int b = gw >> 10, o = gw & 1023;
    const float2* wr = (const float2*)(weight + (size_t)o * CIN);
    const float2* sr = (const float2*)(g_styles + b * CIN);
    float p0[16], p1[16];
    float ss = 0.f;
    #pragma unroll
    for (int t = 0; t < 16; t++) {
        int idx = lane + 32*t;
        float2 wv = wr[idx];
        float2 sv = sr[idx];
        p0[t] = wv.x * sv.x;
        p1[t] = wv.y * sv.y;
        ss += p0[t]*p0[t] + p1[t]*p1[t];
    }
    #pragma unroll
    for (int off = 16; off > 0; off >>= 1) ss += __shfl_xor_sync(0xFFFFFFFFu, ss, off);
    float d = rsqrtf(ss + 1e-8f);
    __nv_bfloat162* dst = (__nv_bfloat162*)(g_wmod + ((size_t)b * COUT + o) * CIN);
    #pragma unroll
    for (int t = 0; t < 16; t++) {
        int idx = lane + 32*t;
        float2 v; v.x = p0[t]*d; v.y = p1[t]*d;
        dst[idx] = __float22bfloat162_rn(v);
    }
}

// =====================================================================
// k2: x (fp32) -> g_xbf (bf16)
// =====================================================================
__global__ void k_xconv(const float* __restrict__ x) {
    size_t n4 = (size_t)MTOT * CIN / 4;
    size_t stride = (size_t)gridDim.x * blockDim.x;
    const float4* xv = (const float4*)x;
    uint2* dst = (uint2*)g_xbf;
    for (size_t i = (size_t)blockIdx.x * blockDim.x + threadIdx.x; i < n4; i += stride) {
        float4 v = xv[i];
        __nv_bfloat162 a = __float22bfloat162_rn(make_float2(v.x, v.y));
        __nv_bfloat162 c = __float22bfloat162_rn(make_float2(v.z, v.w));
        uint2 u;
        u.x = *reinterpret_cast<uint32_t*>(&a);
        u.y = *reinterpret_cast<uint32_t*>(&c);
        dst[i] = u;
    }
}

// =====================================================================
// k3: GEMM  out[m, n] = epilogue( xbf[m,:] @ wmod[b]^T )
// CTA 128(M) x 256(N), K-tile 64; 8 warps in 2x4, warp tile 64x64
// 4-stage cp.async ring (48 KB/stage: A 16KB + B 32KB), SW128, ldmatrix.x4
// grid (N=4, M=256): n fastest -> 4 CTAs of a wave share each A panel (L2 reuse)
// =====================================================================
#define STAGES      4
#define STAGE_BYTES 49152     // A 16KB + B 32KB
#define B_OFF       16384u

DI void load_stage(const __nv_bfloat16* __restrict__ gA, const __nv_bfloat16* __restrict__ gB,
                   uint32_t st, int kt, int tid) {
    const __nv_bfloat16* sA = gA + kt * KT;
    #pragma unroll
    for (int i = 0; i < 4; i++) {                 // A: 128 rows x 8 segs = 1024
        int t = tid + i * 256;
        int row = t >> 3, c = t & 7;
        uint32_t off = (uint32_t)row * 128u + (uint32_t)c * 16u;
        cp16(st + (off ^ ((off >> 3) & 0x70u)), sA + (size_t)row * CIN + c * 8);
    }
    const __nv_bfloat16* sB = gB + kt * KT;
    #pragma unroll
    for (int i = 0; i < 8; i++) {                 // B: 256 rows x 8 segs = 2048
        int t = tid + i * 256;
        int row = t >> 3, c = t & 7;
        uint32_t off = (uint32_t)row * 128u + (uint32_t)c * 16u;
        cp16(st + B_OFF + (off ^ ((off >> 3) & 0x70u)), sB + (size_t)row * CIN + c * 8);
    }
}

__global__ void __launch_bounds__(256, 1)
k_gemm(const float* __restrict__ x, const float* __restrict__ bias,
       const float* __restrict__ ls, float* __restrict__ out) {
    extern __shared__ __align__(1024) char smem[];
    uint32_t sb = smem_u32(smem);
    const int tid  = threadIdx.x;
    const int wid  = tid >> 5;
    const int lane = tid & 31;
    const int m0 = blockIdx.y * 128;
    const int n0 = blockIdx.x * 256;
    const int b  = blockIdx.y >> 5;               // 4096 rows per batch
    const __nv_bfloat16* gA = g_xbf  + (size_t)m0 * CIN;
    const __nv_bfloat16* gB = g_wmod + ((size_t)b * COUT + n0) * CIN;

    const int warp_m = wid & 1;                   // 0..1 -> 64-row block
    const int warp_n = wid >> 1;                  // 0..3 -> 64-col block

    const int aRow = warp_m * 64 + (lane & 15);
    const int bRow = warp_n * 64 + (lane & 15);
    const uint32_t halfOff = (uint32_t)(lane >> 4) * 16u;
    const uint32_t rxA = (uint32_t)(aRow & 7) << 4;
    const uint32_t rxB = (uint32_t)(bRow & 7) << 4;
    const uint32_t aBase = (uint32_t)aRow * 128u;
    const uint32_t bBase = B_OFF + (uint32_t)bRow * 128u;

    float acc[4][8][4];
    #pragma unroll
    for (int i = 0; i < 4; i++)
        #pragma unroll
        for (int j = 0; j < 8; j++)
            #pragma unroll
            for (int e = 0; e < 4; e++) acc[i][j][e] = 0.f;

    load_stage(gA, gB, sb + 0 * STAGE_BYTES, 0, tid); cp_commit();
    load_stage(gA, gB, sb + 1 * STAGE_BYTES, 1, tid); cp_commit();
    load_stage(gA, gB, sb + 2 * STAGE_BYTES, 2, tid); cp_commit();

    for (int kt = 0; kt < NK; kt++) {
        cp_wait<2>();
        __syncthreads();
        int jp = kt + 3;
        if (jp < NK)
            load_stage(gA, gB, sb + (jp & 3) * STAGE_BYTES, jp, tid);
        cp_commit();

        uint32_t st = sb + (kt & 3) * STAGE_BYTES;
        #pragma unroll
        for (int ks = 0; ks < 4; ks++) {
            uint32_t kA = ((uint32_t)(ks * 32) + halfOff) ^ rxA;
            uint32_t kB = ((uint32_t)(ks * 32) + halfOff) ^ rxB;
            uint32_t aF[4][4];
            #pragma unroll
            for (int mi = 0; mi < 4; mi++)
                ldm_x4(aF[mi], st + aBase + (uint32_t)mi * 2048u + kA);
            uint32_t bF[4][4];
            #pragma unroll
            for (int njp = 0; njp < 4; njp++)
                ldm_x4(bF[njp], st + bBase + (uint32_t)njp * 2048u + kB);
            #pragma unroll
            for (int mi = 0; mi < 4; mi++) {
                #pragma unroll
                for (int nj = 0; nj < 8; nj++) {
                    int njp = nj >> 1, sel = nj & 1;
                    mma16816(acc[mi][nj], aF[mi], bF[njp][sel], bF[njp][sel | 2]);
                }
            }
        }
    }

    // ---------------- fused epilogue (registers -> global) ----------------
    const float GAIN = 1.41421356237f;
    const int tm0 = m0 + warp_m * 64 + (lane >> 2);
    const int tc0 = n0 + warp_n * 64 + (lane & 3) * 2;
    float2 bi2[8], ls2[8];
    #pragma unroll
    for (int nj = 0; nj < 8; nj++) {
        int col = tc0 + nj * 8;
        bi2[nj] = make_float2(__ldg(bias + col), __ldg(bias + col + 1));
        ls2[nj] = make_float2(__ldg(ls + col),   __ldg(ls + col + 1));
    }
    #pragma unroll
    for (int mi = 0; mi < 4; mi++) {
        #pragma unroll
        for (int h = 0; h < 2; h++) {
            int m = tm0 + mi * 16 + h * 8;
            const float* xr  = x   + (size_t)m * COUT;
            float*       orr = out + (size_t)m * COUT;
            #pragma unroll
            for (int nj = 0; nj < 8; nj++) {
                int col = tc0 + nj * 8;
                float c0 = acc[mi][nj][h * 2 + 0];
                float c1 = acc[mi][nj][h * 2 + 1];
                float2 xv = *(const float2*)(xr + col);
                float t0 = c0 + bi2[nj].x;
                float t1 = c1 + bi2[nj].y;
                t0 = ((t0 > 0.f) ? t0 : 0.2f * t0) * GAIN;
                t1 = ((t1 > 0.f) ? t1 : 0.2f * t1) * GAIN;
                t0 = fminf(fmaxf(t0, -256.f), 256.f);
                t1 = fminf(fmaxf(t1, -256.f), 256.f);
                float2 o2;
                o2.x = t0 * ls2[nj].x + xv.x;
                o2.y = t1 * ls2[nj].y + xv.y;
                *(float2*)(orr + col) = o2;
            }
        }
    }
}

// =====================================================================
// launch
// =====================================================================
extern "C" void kernel_launch(void* const* d_in, const int* in_sizes, int n_in,
                              void* d_out, int out_size) {
    const float* x      = (const float*)d_in[0];
    const float* w      = (const float*)d_in[1];
    const float* weight = (const float*)d_in[2];
    const float* bias   = (const float*)d_in[3];
    const float* aff_w  = (const float*)d_in[4];
    const float* aff_b  = (const float*)d_in[5];
    const float* lscale = (const float*)d_in[6];
    float* out = (float*)d_out;

    cudaFuncSetAttribute(k_gemm, cudaFuncAttributeMaxDynamicSharedMemorySize,
                         STAGES * STAGE_BYTES);

    k_styles<<<1024, 256>>>(w, aff_w, aff_b);
    k_wmod  <<<1024, 256>>>(weight);
    k_xconv <<<4096, 256>>>(x);

    dim3 grid(COUT / 256, MTOT / 128);   // (n=4, m=256): n fastest -> A panel reuse in-wave
    k_gemm<<<grid, 256, STAGES * STAGE_BYTES>>>(x, bias, lscale, out);
}

// round 10
// speedup vs baseline: 1.1579x; 1.0745x over previous
#include <cuda_runtime.h>
#include <cuda_bf16.h>
#include <cstdint>

#define DI __device__ __forceinline__

// ---------------- problem dims ----------------
#define BB    8
#define LL    4096
#define CIN   1024
#define COUT  1024
#define WDIM  512
#define MTOT  (BB*LL)          // 32768
#define NK    16               // K tiles of 64
#define KT    64               // bf16 per K tile (128 bytes)

// ---------------- device scratch (no allocs allowed) ----------------
__device__ __align__(16) float          g_styles[BB*CIN];                     // 32 KB
__device__ __align__(16) __nv_bfloat16  g_wmod[(size_t)BB*COUT*CIN];          // 16 MB
__device__ __align__(16) __nv_bfloat16  g_xbf[(size_t)MTOT*CIN];              // 64 MB

// ---------------- PTX helpers (baseline PTX only: compute_103 target!) ----------------
DI uint32_t smem_u32(const void* p) {
    uint32_t a;
    asm("{ .reg .u64 t; cvta.to.shared.u64 t, %1; cvt.u32.u64 %0, t; }" : "=r"(a) : "l"(p));
    return a;
}
DI void cp16(uint32_t dst, const void* src) {
    asm volatile("cp.async.cg.shared.global [%0], [%1], 16;" :: "r"(dst), "l"(src));
}
DI void cp_commit() { asm volatile("cp.async.commit_group;" ::: "memory"); }
template<int N> DI void cp_wait() { asm volatile("cp.async.wait_group %0;" :: "n"(N) : "memory"); }

DI void ldm_x4(uint32_t* r, uint32_t addr) {
    asm volatile("ldmatrix.sync.aligned.m8n8.x4.shared.b16 {%0,%1,%2,%3}, [%4];"
        : "=r"(r[0]), "=r"(r[1]), "=r"(r[2]), "=r"(r[3]) : "r"(addr));
}
DI void mma16816(float* c, const uint32_t* a, uint32_t b0, uint32_t b1) {
    asm volatile("mma.sync.aligned.m16n8k16.row.col.f32.bf16.bf16.f32 "
        "{%0,%1,%2,%3}, {%4,%5,%6,%7}, {%8,%9}, {%0,%1,%2,%3};"
        : "+f"(c[0]), "+f"(c[1]), "+f"(c[2]), "+f"(c[3])
        : "r"(a[0]), "r"(a[1]), "r"(a[2]), "r"(a[3]), "r"(b0), "r"(b1));
}

// =====================================================================
// k0: styles[b,i] = (w[b,:] . aff_w[i,:]) / sqrt(512) + aff_b[i]
// =====================================================================
__global__ void k_styles(const float* __restrict__ w, const float* __restrict__ aw,
                         const float* __restrict__ ab) {
    int gw   = (blockIdx.x * blockDim.x + threadIdx.x) >> 5;
    int lane = threadIdx.x & 31;
    if (gw >= BB*CIN) return;
    int b = gw >> 10, i = gw & 1023;
    const float* wr = w  + b * WDIM;
    const float* ar = aw + (size_t)i * WDIM;
    float s = 0.f;
    #pragma unroll
    for (int t = 0; t < WDIM/32; t++) {
        int j = lane + 32*t;
        s += wr[j] * ar[j];
    }
    #pragma unroll
    for (int o = 16; o > 0; o >>= 1) s += __shfl_xor_sync(0xFFFFFFFFu, s, o);
    if (lane == 0)
        g_styles[gw] = s * 0.04419417382415922f + ab[i];   // 1/sqrt(512)
}

// =====================================================================
// k1: per (b,o): prod_i = weight[o,i]*styles[b,i];
//     dcoef = rsqrt(sum prod^2 + 1e-8); wmod[b,o,i] = bf16(prod_i * dcoef)
// =====================================================================
__global__ void k_wmod(const float* __restrict__ weight) {
    int gw   = (blockIdx.x * blockDim.x + threadIdx.x) >> 5;
    int lane = threadIdx.x & 31;
    if (gw >= BB*COUT) return;
    int b = gw >> 10, o = gw & 1023;
    const float2* wr = (const float2*)(weight + (size_t)o * CIN);
    const float2* sr = (const float2*)(g_styles + b * CIN);
    float p0[16], p1[16];
    float ss = 0.f;
    #pragma unroll
    for (int t = 0; t < 16; t++) {
        int idx = lane + 32*t;
        float2 wv = wr[idx];
        float2 sv = sr[idx];
        p0[t] = wv.x * sv.x;
        p1[t] = wv.y * sv.y;
        ss += p0[t]*p0[t] + p1[t]*p1[t];
    }
    #pragma unroll
    for (int off = 16; off > 0; off >>= 1) ss += __shfl_xor_sync(0xFFFFFFFFu, ss, off);
    float d = rsqrtf(ss + 1e-8f);
    __nv_bfloat162* dst = (__nv_bfloat162*)(g_wmod + ((size_t)b * COUT + o) * CIN);
    #pragma unroll
    for (int t = 0; t < 16; t++) {
        int idx = lane + 32*t;
        float2 v; v.x = p0[t]*d; v.y = p1[t]*d;
        dst[idx] = __float22bfloat162_rn(v);
    }
}

// =====================================================================
// k2: x (fp32) -> g_xbf (bf16)
// =====================================================================
__global__ void k_xconv(const float* __restrict__ x) {
    size_t n4 = (size_t)MTOT * CIN / 4;
    size_t stride = (size_t)gridDim.x * blockDim.x;
    const float4* xv = (const float4*)x;
    uint2* dst = (uint2*)g_xbf;
    for (size_t i = (size_t)blockIdx.x * blockDim.x + threadIdx.x; i < n4; i += stride) {
        float4 v = xv[i];
        __nv_bfloat162 a = __float22bfloat162_rn(make_float2(v.x, v.y));
        __nv_bfloat162 c = __float22bfloat162_rn(make_float2(v.z, v.w));
        uint2 u;
        u.x = *reinterpret_cast<uint32_t*>(&a);
        u.y = *reinterpret_cast<uint32_t*>(&c);
        dst[i] = u;
    }
}

// =====================================================================
// k3: GEMM  out[m, n] = epilogue( xbf[m,:] @ wmod[b]^T )
// CTA 128x128, K-tile 64; 8 warps (2x4), warp tile 64x32
// 3-stage cp.async ring (32 KB/stage), 96 KB smem/CTA -> 2 CTAs/SM (16 warps)
// __launch_bounds__(256,2) caps regs at 128 for co-residency
// grid (n=8, m=256): n fastest -> 8 CTAs of a wave share each A panel (L2 reuse)
// =====================================================================
#define STAGES      3
#define STAGE_BYTES 32768     // A 16KB + B 16KB
#define B_OFF       16384u

DI void load_stage(const __nv_bfloat16* __restrict__ gA, const __nv_bfloat16* __restrict__ gB,
                   uint32_t st, int kt, int tid) {
    const __nv_bfloat16* sA = gA + kt * KT;
    #pragma unroll
    for (int i = 0; i < 4; i++) {                 // A: 128 rows x 8 segs
        int t = tid + i * 256;
        int row = t >> 3, c = t & 7;
        uint32_t off = (uint32_t)row * 128u + (uint32_t)c * 16u;
        cp16(st + (off ^ ((off >> 3) & 0x70u)), sA + (size_t)row * CIN + c * 8);
    }
    const __nv_bfloat16* sB = gB + kt * KT;
    #pragma unroll
    for (int i = 0; i < 4; i++) {                 // B: 128 rows x 8 segs
        int t = tid + i * 256;
        int row = t >> 3, c = t & 7;
        uint32_t off = (uint32_t)row * 128u + (uint32_t)c * 16u;
        cp16(st + B_OFF + (off ^ ((off >> 3) & 0x70u)), sB + (size_t)row * CIN + c * 8);
    }
}

__global__ void __launch_bounds__(256, 2)
k_gemm(const float* __restrict__ x, const float* __restrict__ bias,
       const float* __restrict__ ls, float* __restrict__ out) {
    extern __shared__ __align__(1024) char smem[];
    uint32_t sb = smem_u32(smem);
    const int tid  = threadIdx.x;
    const int wid  = tid >> 5;
    const int lane = tid & 31;
    const int m0 = blockIdx.y * 128;
    const int n0 = blockIdx.x * 128;
    const int b  = blockIdx.y >> 5;               // 4096 rows per batch
    const __nv_bfloat16* gA = g_xbf  + (size_t)m0 * CIN;
    const __nv_bfloat16* gB = g_wmod + ((size_t)b * COUT + n0) * CIN;

    const int warp_m = wid & 1;                   // 0..1 -> 64-row block
    const int warp_n = wid >> 1;                  // 0..3 -> 32-col block

    const int aRow = warp_m * 64 + (lane & 15);
    const int bRow = warp_n * 32 + (lane & 15);
    const uint32_t halfOff = (uint32_t)(lane >> 4) * 16u;
    const uint32_t rxA = (uint32_t)(aRow & 7) << 4;
    const uint32_t rxB = (uint32_t)(bRow & 7) << 4;
    const uint32_t aBase = (uint32_t)aRow * 128u;
    const uint32_t bBase = B_OFF + (uint32_t)bRow * 128u;

    float acc[4][4][4];
    #pragma unroll
    for (int i = 0; i < 4; i++)
        #pragma unroll
        for (int j = 0; j < 4; j++)
            #pragma unroll
            for (int e = 0; e < 4; e++) acc[i][j][e] = 0.f;

    load_stage(gA, gB, sb + 0 * STAGE_BYTES, 0, tid); cp_commit();
    load_stage(gA, gB, sb + 1 * STAGE_BYTES, 1, tid); cp_commit();

    uint32_t stg = 0;
    for (int kt = 0; kt < NK; kt++) {
        cp_wait<1>();
        __syncthreads();
        int jp = kt + 2;
        uint32_t pstg = stg + 2; if (pstg >= STAGES) pstg -= STAGES;
        if (jp < NK)
            load_stage(gA, gB, sb + pstg * STAGE_BYTES, jp, tid);
        cp_commit();

        uint32_t st = sb + stg * STAGE_BYTES;
        if (++stg == STAGES) stg = 0;
        #pragma unroll
        for (int ks = 0; ks < 4; ks++) {
            uint32_t kA = ((uint32_t)(ks * 32) + halfOff) ^ rxA;
            uint32_t kB = ((uint32_t)(ks * 32) + halfOff) ^ rxB;
            uint32_t aF[4][4];
            #pragma unroll
            for (int mi = 0; mi < 4; mi++)
                ldm_x4(aF[mi], st + aBase + (uint32_t)mi * 2048u + kA);
            uint32_t bF[2][4];
            #pragma unroll
            for (int njp = 0; njp < 2; njp++)
                ldm_x4(bF[njp], st + bBase + (uint32_t)njp * 2048u + kB);
            #pragma unroll
            for (int mi = 0; mi < 4; mi++) {
                #pragma unroll
                for (int nj = 0; nj < 4; nj++) {
                    int njp = nj >> 1, sel = nj & 1;
                    mma16816(acc[mi][nj], aF[mi], bF[njp][sel], bF[njp][sel | 2]);
                }
            }
        }
    }

    // ---------------- fused epilogue (registers -> global) ----------------
    const float GAIN = 1.41421356237f;
    const int tm0 = m0 + warp_m * 64 + (lane >> 2);
    const int tc0 = n0 + warp_n * 32 + (lane & 3) * 2;
    #pragma unroll
    for (int mi = 0; mi < 4; mi++) {
        #pragma unroll
        for (int h = 0; h < 2; h++) {
            int m = tm0 + mi * 16 + h * 8;
            const float* xr  = x   + (size_t)m * COUT;
            float*       orr = out + (size_t)m * COUT;
            #pragma unroll
            for (int nj = 0; nj < 4; nj++) {
                int col = tc0 + nj * 8;
                float c0 = acc[mi][nj][h * 2 + 0];
                float c1 = acc[mi][nj][h * 2 + 1];
                float2 xv = *(const float2*)(xr + col);
                float t0 = c0 + __ldg(bias + col);
                float t1 = c1 + __ldg(bias + col + 1);
                t0 = ((t0 > 0.f) ? t0 : 0.2f * t0) * GAIN;
                t1 = ((t1 > 0.f) ? t1 : 0.2f * t1) * GAIN;
                t0 = fminf(fmaxf(t0, -256.f), 256.f);
                t1 = fminf(fmaxf(t1, -256.f), 256.f);
                float2 o2;
                o2.x = t0 * __ldg(ls + col)     + xv.x;
                o2.y = t1 * __ldg(ls + col + 1) + xv.y;
                *(float2*)(orr + col) = o2;
            }
        }
    }
}

// =====================================================================
// launch
// =====================================================================
extern "C" void kernel_launch(void* const* d_in, const int* in_sizes, int n_in,
                              void* d_out, int out_size) {
    const float* x      = (const float*)d_in[0];
    const float* w      = (const float*)d_in[1];
    const float* weight = (const float*)d_in[2];
    const float* bias   = (const float*)d_in[3];
    const float* aff_w  = (const float*)d_in[4];
    const float* aff_b  = (const float*)d_in[5];
    const float* lscale = (const float*)d_in[6];
    float* out = (float*)d_out;

    cudaFuncSetAttribute(k_gemm, cudaFuncAttributeMaxDynamicSharedMemorySize,
                         STAGES * STAGE_BYTES);

    k_styles<<<1024, 256>>>(w, aff_w, aff_b);
    k_wmod  <<<1024, 256>>>(weight);
    k_xconv <<<4096, 256>>>(x);

    dim3 grid(COUT / 128, MTOT / 128);   // (n=8, m=256): n fastest -> A panel reuse in-wave
    k_gemm<<<grid, 256, STAGES * STAGE_BYTES>>>(x, bias, lscale, out);
}

// round 12
// speedup vs baseline: 1.1868x; 1.0250x over previous
#include <cuda_runtime.h>
#include <cuda_bf16.h>
#include <cstdint>

#define DI __device__ __forceinline__

// ---------------- problem dims ----------------
#define BB    8
#define LL    4096
#define CIN   1024
#define COUT  1024
#define WDIM  512
#define MTOT  (BB*LL)          // 32768
#define NK    16               // K tiles of 64
#define KT    64               // bf16 per K tile (128 bytes)

// ---------------- device scratch (no allocs allowed) ----------------
__device__ __align__(16) float          g_styles[BB*CIN];                     // 32 KB
__device__ __align__(16) __nv_bfloat16  g_wmod[(size_t)BB*COUT*CIN];          // 16 MB
__device__ __align__(16) __nv_bfloat16  g_xbf[(size_t)MTOT*CIN];              // 64 MB

// ---------------- PTX helpers (baseline PTX only: compute_103 target!) ----------------
DI uint32_t smem_u32(const void* p) {
    uint32_t a;
    asm("{ .reg .u64 t; cvta.to.shared.u64 t, %1; cvt.u32.u64 %0, t; }" : "=r"(a) : "l"(p));
    return a;
}
DI void cp16(uint32_t dst, const void* src) {
    asm volatile("cp.async.cg.shared.global [%0], [%1], 16;" :: "r"(dst), "l"(src));
}
DI void mbar_init(uint32_t a, uint32_t cnt) {
    asm volatile("mbarrier.init.shared.b64 [%0], %1;" :: "r"(a), "r"(cnt) : "memory");
}
DI void mbar_arrive(uint32_t a) {
    asm volatile("mbarrier.arrive.shared.b64 _, [%0];" :: "r"(a) : "memory");
}
// .noinc is REQUIRED: the default form increments the pending count at issue and
// decrements on completion (net zero arrivals) -> the init count is never consumed
// -> deadlock (round-11 hang). With .noinc each thread's cp-group completion is
// exactly one arrival against the init count.
DI void cp_arrive(uint32_t a) {
    asm volatile("cp.async.mbarrier.arrive.noinc.shared.b64 [%0];" :: "r"(a) : "memory");
}
DI void mbar_wait(uint32_t a, uint32_t parity) {
    uint32_t done;
    asm volatile("{ .reg .pred p; mbarrier.try_wait.parity.acquire.cta.shared::cta.b64 p, [%1], %2; selp.b32 %0,1,0,p; }"
        : "=r"(done) : "r"(a), "r"(parity) : "memory");
    if (!done) {
        asm volatile("{ .reg .pred P1; WL_%=: mbarrier.try_wait.parity.acquire.cta.shared::cta.b64 P1, [%0], %1, 0x989680; @P1 bra.uni WD_%=; bra.uni WL_%=; WD_%=: }"
            :: "r"(a), "r"(parity) : "memory");
    }
}

DI void ldm_x4(uint32_t* r, uint32_t addr) {
    asm volatile("ldmatrix.sync.aligned.m8n8.x4.shared.b16 {%0,%1,%2,%3}, [%4];"
        : "=r"(r[0]), "=r"(r[1]), "=r"(r[2]), "=r"(r[3]) : "r"(addr));
}
DI void mma16816(float* c, const uint32_t* a, uint32_t b0, uint32_t b1) {
    asm volatile("mma.sync.aligned.m16n8k16.row.col.f32.bf16.bf16.f32 "
        "{%0,%1,%2,%3}, {%4,%5,%6,%7}, {%8,%9}, {%0,%1,%2,%3};"
        : "+f"(c[0]), "+f"(c[1]), "+f"(c[2]), "+f"(c[3])
        : "r"(a[0]), "r"(a[1]), "r"(a[2]), "r"(a[3]), "r"(b0), "r"(b1));
}

// =====================================================================
// k0: styles[b,i] = (w[b,:] . aff_w[i,:]) / sqrt(512) + aff_b[i]
// =====================================================================
__global__ void k_styles(const float* __restrict__ w, const float* __restrict__ aw,
                         const float* __restrict__ ab) {
    int gw   = (blockIdx.x * blockDim.x + threadIdx.x) >> 5;
    int lane = threadIdx.x & 31;
    if (gw >= BB*CIN) return;
    int b = gw >> 10, i = gw & 1023;
    const float* wr = w  + b * WDIM;
    const float* ar = aw + (size_t)i * WDIM;
    float s = 0.f;
    #pragma unroll
    for (int t = 0; t < WDIM/32; t++) {
        int j = lane + 32*t;
        s += wr[j] * ar[j];
    }
    #pragma unroll
    for (int o = 16; o > 0; o >>= 1) s += __shfl_xor_sync(0xFFFFFFFFu, s, o);
    if (lane == 0)
        g_styles[gw] = s * 0.04419417382415922f + ab[i];   // 1/sqrt(512)
}

// =====================================================================
// k1: per (b,o): prod_i = weight[o,i]*styles[b,i];
//     dcoef = rsqrt(sum prod^2 + 1e-8); wmod[b,o,i] = bf16(prod_i * dcoef)
// =====================================================================
__global__ void k_wmod(const float* __restrict__ weight) {
    int gw   = (blockIdx.x * blockDim.x + threadIdx.x) >> 5;
    int lane = threadIdx.x & 31;
    if (gw >= BB*COUT) return;
    int b = gw >> 10, o = gw & 1023;
    const float2* wr = (const float2*)(weight + (size_t)o * CIN);
    const float2* sr = (const float2*)(g_styles + b * CIN);
    float p0[16], p1[16];
    float ss = 0.f;
    #pragma unroll
    for (int t = 0; t < 16; t++) {
        int idx = lane + 32*t;
        float2 wv = wr[idx];
        float2 sv = sr[idx];
        p0[t] = wv.x * sv.x;
        p1[t] = wv.y * sv.y;
        ss += p0[t]*p0[t] + p1[t]*p1[t];
    }
    #pragma unroll
    for (int off = 16; off > 0; off >>= 1) ss += __shfl_xor_sync(0xFFFFFFFFu, ss, off);
    float d = rsqrtf(ss + 1e-8f);
    __nv_bfloat162* dst = (__nv_bfloat162*)(g_wmod + ((size_t)b * COUT + o) * CIN);
    #pragma unroll
    for (int t = 0; t < 16; t++) {
        int idx = lane + 32*t;
        float2 v; v.x = p0[t]*d; v.y = p1[t]*d;
        dst[idx] = __float22bfloat162_rn(v);
    }
}

// =====================================================================
// k2: x (fp32) -> g_xbf (bf16)
// =====================================================================
__global__ void k_xconv(const float* __restrict__ x) {
    size_t n4 = (size_t)MTOT * CIN / 4;
    size_t stride = (size_t)gridDim.x * blockDim.x;
    const float4* xv = (const float4*)x;
    uint2* dst = (uint2*)g_xbf;
    for (size_t i = (size_t)blockIdx.x * blockDim.x + threadIdx.x; i < n4; i += stride) {
        float4 v = xv[i];
        __nv_bfloat162 a = __float22bfloat162_rn(make_float2(v.x, v.y));
        __nv_bfloat162 c = __float22bfloat162_rn(make_float2(v.z, v.w));
        uint2 u;
        u.x = *reinterpret_cast<uint32_t*>(&a);
        u.y = *reinterpret_cast<uint32_t*>(&c);
        dst[i] = u;
    }
}

// =====================================================================
// k3: GEMM  out[m, n] = epilogue( xbf[m,:] @ wmod[b]^T )
// CTA 128x128, K-tile 64; 8 warps (2x4), warp tile 64x32
// 3-stage ring with mbarrier producer/consumer tracking (NO __syncthreads
// in the mainloop -> no warp convoy; warps slip within the 3-stage window)
// 97 KB smem/CTA, __launch_bounds__(256,2) -> 2 CTAs/SM (16 warps)
// grid (n=8, m=256): n fastest -> 8 CTAs of a wave share each A panel (L2 reuse)
// =====================================================================
#define STAGES      3
#define STAGE_BYTES 32768     // A 16KB + B 16KB
#define B_OFF       16384u
#define MBAR_REGION 1024      // mbarriers live here; buffers after
#define SMEM_TOTAL  (MBAR_REGION + STAGES * STAGE_BYTES)

// full(s) = sb + s*16, empty(s) = sb + s*16 + 8
DI void produce_stage(const __nv_bfloat16* __restrict__ gA, const __nv_bfloat16* __restrict__ gB,
                      uint32_t st, int kt, int tid) {
    const __nv_bfloat16* sA = gA + kt * KT;
    #pragma unroll
    for (int i = 0; i < 4; i++) {                 // A: 128 rows x 8 segs
        int t = tid + i * 256;
        int row = t >> 3, c = t & 7;
        uint32_t off = (uint32_t)row * 128u + (uint32_t)c * 16u;
        cp16(st + (off ^ ((off >> 3) & 0x70u)), sA + (size_t)row * CIN + c * 8);
    }
    const __nv_bfloat16* sB = gB + kt * KT;
    #pragma unroll
    for (int i = 0; i < 4; i++) {                 // B: 128 rows x 8 segs
        int t = tid + i * 256;
        int row = t >> 3, c = t & 7;
        uint32_t off = (uint32_t)row * 128u + (uint32_t)c * 16u;
        cp16(st + B_OFF + (off ^ ((off >> 3) & 0x70u)), sB + (size_t)row * CIN + c * 8);
    }
}

__global__ void __launch_bounds__(256, 2)
k_gemm(const float* __restrict__ x, const float* __restrict__ bias,
       const float* __restrict__ ls, float* __restrict__ out) {
    extern __shared__ __align__(1024) char smem[];
    uint32_t sb   = smem_u32(smem);
    uint32_t bufs = sb + MBAR_REGION;
    const int tid  = threadIdx.x;
    const int wid  = tid >> 5;
    const int lane = tid & 31;
    const int m0 = blockIdx.y * 128;
    const int n0 = blockIdx.x * 128;
    const int b  = blockIdx.y >> 5;               // 4096 rows per batch
    const __nv_bfloat16* gA = g_xbf  + (size_t)m0 * CIN;
    const __nv_bfloat16* gB = g_wmod + ((size_t)b * COUT + n0) * CIN;

    if (tid == 0) {
        #pragma unroll
        for (int s = 0; s < STAGES; s++) {
            mbar_init(sb + s * 16,     256);      // full: one arrival per thread's cp-group (noinc)
            mbar_init(sb + s * 16 + 8, 256);      // empty: all 256 threads done reading
        }
    }
    __syncthreads();                              // only CTA-wide barrier in the kernel

    const int warp_m = wid & 1;                   // 0..1 -> 64-row block
    const int warp_n = wid >> 1;                  // 0..3 -> 32-col block

    const int aRow = warp_m * 64 + (lane & 15);
    const int bRow = warp_n * 32 + (lane & 15);
    const uint32_t halfOff = (uint32_t)(lane >> 4) * 16u;
    const uint32_t rxA = (uint32_t)(aRow & 7) << 4;
    const uint32_t rxB = (uint32_t)(bRow & 7) << 4;
    const uint32_t aBase = (uint32_t)aRow * 128u;
    const uint32_t bBase = B_OFF + (uint32_t)bRow * 128u;

    float acc[4][4][4];
    #pragma unroll
    for (int i = 0; i < 4; i++)
        #pragma unroll
        for (int j = 0; j < 4; j++)
            #pragma unroll
            for (int e = 0; e < 4; e++) acc[i][j][e] = 0.f;

    // prologue: produce ktiles 0,1 into stages 0,1
    produce_stage(gA, gB, bufs + 0 * STAGE_BYTES, 0, tid); cp_arrive(sb + 0 * 16);
    produce_stage(gA, gB, bufs + 1 * STAGE_BYTES, 1, tid); cp_arrive(sb + 1 * 16);

    // cursors
    int ps = 2, pph = 1;    // producer: next target stage / empty-wait parity (starts "pass immediately")
    int cs = 0, cph = 0;    // consumer: stage / full-wait parity

    for (int kt = 0; kt < NK; kt++) {
        int jp = kt + 2;
        if (jp < NK) {
            mbar_wait(sb + ps * 16 + 8, (uint32_t)pph);         // wait stage empty
            produce_stage(gA, gB, bufs + (uint32_t)ps * STAGE_BYTES, jp, tid);
            cp_arrive(sb + ps * 16);                            // arrive full on cp completion (noinc)
            if (++ps == STAGES) { ps = 0; pph ^= 1; }
        }

        mbar_wait(sb + cs * 16, (uint32_t)cph);                 // wait stage full (acquire)
        uint32_t st = bufs + (uint32_t)cs * STAGE_BYTES;
        #pragma unroll
        for (int ks = 0; ks < 4; ks++) {
            uint32_t kA = ((uint32_t)(ks * 32) + halfOff) ^ rxA;
            uint32_t kB = ((uint32_t)(ks * 32) + halfOff) ^ rxB;
            uint32_t aF[4][4];
            #pragma unroll
            for (int mi = 0; mi < 4; mi++)
                ldm_x4(aF[mi], st + aBase + (uint32_t)mi * 2048u + kA);
            uint32_t bF[2][4];
            #pragma unroll
            for (int njp = 0; njp < 2; njp++)
                ldm_x4(bF[njp], st + bBase + (uint32_t)njp * 2048u + kB);
            #pragma unroll
            for (int mi = 0; mi < 4; mi++) {
                #pragma unroll
                for (int nj = 0; nj < 4; nj++) {
                    int njp = nj >> 1, sel = nj & 1;
                    mma16816(acc[mi][nj], aF[mi], bF[njp][sel], bF[njp][sel | 2]);
                }
            }
        }
        mbar_arrive(sb + cs * 16 + 8);                          // this thread done with stage
        if (++cs == STAGES) { cs = 0; cph ^= 1; }
    }

    // ---------------- fused epilogue (registers -> global) ----------------
    const float GAIN = 1.41421356237f;
    const int tm0 = m0 + warp_m * 64 + (lane >> 2);
    const int tc0 = n0 + warp_n * 32 + (lane & 3) * 2;
    #pragma unroll
    for (int mi = 0; mi < 4; mi++) {
        #pragma unroll
        for (int h = 0; h < 2; h++) {
            int m = tm0 + mi * 16 + h * 8;
            const float* xr  = x   + (size_t)m * COUT;
            float*       orr = out + (size_t)m * COUT;
            #pragma unroll
            for (int nj = 0; nj < 4; nj++) {
                int col = tc0 + nj * 8;
                float c0 = acc[mi][nj][h * 2 + 0];
                float c1 = acc[mi][nj][h * 2 + 1];
                float2 xv = *(const float2*)(xr + col);
                float t0 = c0 + __ldg(bias + col);
                float t1 = c1 + __ldg(bias + col + 1);
                t0 = ((t0 > 0.f) ? t0 : 0.2f * t0) * GAIN;
                t1 = ((t1 > 0.f) ? t1 : 0.2f * t1) * GAIN;
                t0 = fminf(fmaxf(t0, -256.f), 256.f);
                t1 = fminf(fmaxf(t1, -256.f), 256.f);
                float2 o2;
                o2.x = t0 * __ldg(ls + col)     + xv.x;
                o2.y = t1 * __ldg(ls + col + 1) + xv.y;
                *(float2*)(orr + col) = o2;
            }
        }
    }
}

// =====================================================================
// launch
// =====================================================================
extern "C" void kernel_launch(void* const* d_in, const int* in_sizes, int n_in,
                              void* d_out, int out_size) {
    const float* x      = (const float*)d_in[0];
    const float* w      = (const float*)d_in[1];
    const float* weight = (const float*)d_in[2];
    const float* bias   = (const float*)d_in[3];
    const float* aff_w  = (const float*)d_in[4];
    const float* aff_b  = (const float*)d_in[5];
    const float* lscale = (const float*)d_in[6];
    float* out = (float*)d_out;

    cudaFuncSetAttribute(k_gemm, cudaFuncAttributeMaxDynamicSharedMemorySize, SMEM_TOTAL);

    k_styles<<<1024, 256>>>(w, aff_w, aff_b);
    k_wmod  <<<1024, 256>>>(weight);
    k_xconv <<<4096, 256>>>(x);

    dim3 grid(COUT / 128, MTOT / 128);   // (n=8, m=256): n fastest -> A panel reuse in-wave
    k_gemm<<<grid, 256, SMEM_TOTAL>>>(x, bias, lscale, out);
}